// round 16
// baseline (speedup 1.0000x reference)
#include <cuda_runtime.h>
#include <math.h>
#include <stdint.h>

// Problem constants (fixed by the reference)
#define HH   8      // heads
#define CC   32     // channels per head
#define HC   256    // H*C
#define FE   16     // edge feature dim
#define FIN  128    // input feature dim
#define NEG  0.2f

#define MAXN 50000
#define MAXE 800000

// ---------------- device scratch (no allocs allowed) ----------------
__device__ __align__(16) float g_xh[(size_t)MAXN * HC];   // projected node features [N,H,C]
__device__ __align__(16) float g_asrc[MAXN * HH];
__device__ __align__(16) float g_adst[MAXN * HH];
__device__ __align__(16) float g_denom[MAXN * HH];
__device__ __align__(16) float g_loop[MAXN * FE];
__device__ float g_deg[MAXN];
__device__ __align__(16) float g_alpha[(size_t)MAXE * HH]; // per-edge exp(leaky(alpha))
__device__ int   g_src[MAXE];
__device__ int   g_dst[MAXE];
__device__ float g_M[FE * HH];                 // folded edge-attention matrix [F_e,H]
__device__ int   g_is64;

// ---------------- packed f32x2 helpers (sm_103a FFMA2) ----------------
__device__ __forceinline__ unsigned long long dup2(float a) {
    unsigned long long r;
    asm("mov.b64 %0, {%1, %1};" : "=l"(r) : "f"(a));
    return r;
}
__device__ __forceinline__ void ffma2(unsigned long long& d,
                                      unsigned long long a,
                                      unsigned long long b) {
    asm("fma.rn.f32x2 %0, %1, %2, %0;" : "+l"(d) : "l"(a), "l"(b));
}

// ---------------- K0: detect edge_index dtype (int64 vs int32) ----------------
__global__ void k_detect(const unsigned int* __restrict__ w, int nwords) {
    __shared__ unsigned int s[256];
    unsigned int acc = 0;
    for (int t = threadIdx.x; t < 1024; t += 256) {
        int idx = 2 * t + 1;
        if (idx < nwords) acc |= w[idx];
    }
    s[threadIdx.x] = acc;
    __syncthreads();
    for (int o = 128; o > 0; o >>= 1) {
        if (threadIdx.x < o) s[threadIdx.x] |= s[threadIdx.x + o];
        __syncthreads();
    }
    if (threadIdx.x == 0) g_is64 = (s[0] == 0u) ? 1 : 0;
}

// ---------------- K1: convert indices to int32 scratch ----------------
__global__ void k_convert(const void* __restrict__ ei, int E) {
    int e = blockIdx.x * blockDim.x + threadIdx.x;
    if (e >= E) return;
    int s, d;
    if (g_is64) {
        const long long* p = (const long long*)ei;
        s = (int)p[e];
        d = (int)p[(size_t)E + e];
    } else {
        const int* p = (const int*)ei;
        s = p[e];
        d = p[E + e];
    }
    g_src[e] = s;
    g_dst[e] = d;
}

// ---------------- K2: folded edge-attn matrix M[f,h] ----------------
__global__ void k_M(const float* __restrict__ We, const float* __restrict__ ae) {
    int t = threadIdx.x;
    if (t >= FE * HH) return;
    int f = t / HH, h = t % HH;
    float s = 0.0f;
    #pragma unroll
    for (int c = 0; c < CC; c++)
        s = fmaf(We[(h * CC + c) * FE + f], ae[h * CC + c], s);
    g_M[f * HH + h] = s;
}

// ---------------- K3: init accumulators ----------------
__global__ void k_init(int N) {
    int i = blockIdx.x * blockDim.x + threadIdx.x;
    if (i < N * FE) g_loop[i] = 0.0f;
    if (i < N * HH) g_denom[i] = 0.0f;
    if (i < N) g_deg[i] = 0.0f;
}

// ---------------- K4: GEMM xh = x @ W^T  via packed f32x2 ----------------
// Tile: 128 rows x 128 cols per CTA, 256 threads, 8 rows x 4 col-pairs per thread.
// 2 CTAs/SM (72KB smem each).
__global__ void __launch_bounds__(256, 2) k_gemm(const float* __restrict__ x,
                                                 const float* __restrict__ W,
                                                 int N) {
    extern __shared__ float sm[];
    float* ws = sm;                 // [128 k][128 c]  ws[k*128 + c]
    float* xs = sm + FIN * 128;     // [16 k][128 r]   xs[kk*128 + r]
    int tid = threadIdx.x;
    int tx  = tid & 15;             // col-pair group
    int ty  = tid >> 4;             // row group
    int rb  = blockIdx.x * 128;
    int cb  = blockIdx.y * 128;

    // load W tile: cols cb..cb+127, k = 0..127 (each thread: one col, half the k's)
    {
        int c  = tid & 127;
        int kh = (tid >> 7) * 64;
        const float* wp = W + (size_t)(cb + c) * FIN + kh;
        #pragma unroll
        for (int k4 = 0; k4 < 16; k4++) {
            float4 w = *(const float4*)(wp + k4 * 4);
            ws[(kh + k4 * 4 + 0) * 128 + c] = w.x;
            ws[(kh + k4 * 4 + 1) * 128 + c] = w.y;
            ws[(kh + k4 * 4 + 2) * 128 + c] = w.z;
            ws[(kh + k4 * 4 + 3) * 128 + c] = w.w;
        }
    }

    unsigned long long acc[8][4];
    #pragma unroll
    for (int i = 0; i < 8; i++)
        #pragma unroll
        for (int j = 0; j < 4; j++) acc[i][j] = 0ull;

    for (int kb = 0; kb < FIN / 16; kb++) {
        __syncthreads();   // also covers W visibility on first iteration
        {
            int r   = tid >> 1;
            int kq  = (tid & 1) * 8;
            int row = rb + r;
            if (row >= N) row = N - 1;          // clamp (stores are guarded)
            const float* xp = x + (size_t)row * FIN + kb * 16 + kq;
            float4 v0 = *(const float4*)(xp);
            float4 v1 = *(const float4*)(xp + 4);
            xs[(kq + 0) * 128 + r] = v0.x;
            xs[(kq + 1) * 128 + r] = v0.y;
            xs[(kq + 2) * 128 + r] = v0.z;
            xs[(kq + 3) * 128 + r] = v0.w;
            xs[(kq + 4) * 128 + r] = v1.x;
            xs[(kq + 5) * 128 + r] = v1.y;
            xs[(kq + 6) * 128 + r] = v1.z;
            xs[(kq + 7) * 128 + r] = v1.w;
        }
        __syncthreads();
        #pragma unroll
        for (int kk = 0; kk < 16; kk++) {
            unsigned long long x2[8], w2[4];
            #pragma unroll
            for (int i = 0; i < 8; i++)
                x2[i] = dup2(xs[kk * 128 + ty * 8 + i]);
            #pragma unroll
            for (int j = 0; j < 4; j++)
                w2[j] = *(const unsigned long long*)(ws + (kb * 16 + kk) * 128 + 2 * tx + 32 * j);
            #pragma unroll
            for (int i = 0; i < 8; i++)
                #pragma unroll
                for (int j = 0; j < 4; j++)
                    ffma2(acc[i][j], x2[i], w2[j]);
        }
    }

    #pragma unroll
    for (int i = 0; i < 8; i++) {
        int row = rb + ty * 8 + i;
        if (row < N) {
            #pragma unroll
            for (int j = 0; j < 4; j++) {
                float2 v = *(float2*)&acc[i][j];  // lo = col 2*tx, hi = col 2*tx+1
                *(float2*)(g_xh + (size_t)row * HC + cb + 2 * tx + 32 * j) = v;
            }
        }
    }
}

// ---------------- K5: per-node a_src / a_dst ----------------
__global__ void k_att_nodes(const float* __restrict__ asrc_w,
                            const float* __restrict__ adst_w, int N) {
    int t = blockIdx.x * blockDim.x + threadIdx.x;
    if (t >= N * HH) return;
    int n = t >> 3, h = t & 7;
    const float* row = g_xh + (size_t)n * HC + h * CC;
    float s = 0.0f, d = 0.0f;
    #pragma unroll
    for (int c = 0; c < CC; c++) {
        float v = row[c];
        s = fmaf(v, __ldg(asrc_w + h * CC + c), s);
        d = fmaf(v, __ldg(adst_w + h * CC + c), d);
    }
    g_asrc[t] = s;
    g_adst[t] = d;
}

// ---------------- K6: fused per-edge alpha->exp + denom + deg + loop_attr ----------------
// No softmax-max needed: |alpha| is small, exp(alpha)/sum(exp) == softmax exactly.
__global__ void k_edge1(const float* __restrict__ ea, int E) {
    __shared__ float Ms[FE * HH];
    if (threadIdx.x < FE * HH) Ms[threadIdx.x] = g_M[threadIdx.x];
    __syncthreads();
    int e = blockIdx.x * blockDim.x + threadIdx.x;
    if (e >= E) return;
    int s = g_src[e], d = g_dst[e];

    float4 av[4];
    const float4* p = (const float4*)(ea + (size_t)e * FE);
    #pragma unroll
    for (int q = 0; q < 4; q++) av[q] = p[q];
    float a[FE];
    *(float4*)(a + 0)  = av[0];
    *(float4*)(a + 4)  = av[1];
    *(float4*)(a + 8)  = av[2];
    *(float4*)(a + 12) = av[3];

    float4 s0 = *(const float4*)(g_asrc + s * HH);
    float4 s1 = *(const float4*)(g_asrc + s * HH + 4);
    float4 d0 = *(const float4*)(g_adst + d * HH);
    float4 d1 = *(const float4*)(g_adst + d * HH + 4);
    float sa[8] = {s0.x, s0.y, s0.z, s0.w, s1.x, s1.y, s1.z, s1.w};
    float da[8] = {d0.x, d0.y, d0.z, d0.w, d1.x, d1.y, d1.z, d1.w};

    float ex[8];
    #pragma unroll
    for (int h = 0; h < HH; h++) {
        float aeh = 0.0f;
        #pragma unroll
        for (int f = 0; f < FE; f++) aeh = fmaf(a[f], Ms[f * HH + h], aeh);
        float al = sa[h] + da[h] + aeh;
        al = (al >= 0.0f) ? al : NEG * al;
        ex[h] = __expf(al);
    }
    float4 e0 = make_float4(ex[0], ex[1], ex[2], ex[3]);
    float4 e1 = make_float4(ex[4], ex[5], ex[6], ex[7]);
    *(float4*)(g_alpha + (size_t)e * HH)     = e0;
    *(float4*)(g_alpha + (size_t)e * HH + 4) = e1;

    atomicAdd((float4*)(g_denom + d * HH),     e0);
    atomicAdd((float4*)(g_denom + d * HH + 4), e1);
    #pragma unroll
    for (int q = 0; q < 4; q++)
        atomicAdd((float4*)(g_loop + d * FE + q * 4), av[q]);
    atomicAdd(&g_deg[d], 1.0f);
}

// ---------------- K7: per-node self-loop + finalize denom + output init ----------------
// One warp per node. Lane = output channel. Lanes 0..7 also handle heads.
__global__ void k_node_out(const float* __restrict__ bias, float* __restrict__ out, int N) {
    int lane = threadIdx.x & 31;
    int n = (blockIdx.x * blockDim.x + threadIdx.x) >> 5;
    if (n >= N) return;
    float att = 0.0f;
    float invdeg = 1.0f / fmaxf(g_deg[n], 1.0f);
    if (lane < HH) {
        int h = lane;
        float aeh = 0.0f;
        #pragma unroll
        for (int f = 0; f < FE; f++)
            aeh = fmaf(g_loop[n * FE + f] * invdeg, g_M[f * HH + h], aeh);
        float al = g_asrc[n * HH + h] + g_adst[n * HH + h] + aeh;
        al = (al >= 0.0f) ? al : NEG * al;
        float ex  = __expf(al);
        float den = g_denom[n * HH + h] + ex;
        g_denom[n * HH + h] = den;        // finalize denom for K8
        att = ex / den * (1.0f / HH);
    }
    float atth[HH];
    #pragma unroll
    for (int h = 0; h < HH; h++) atth[h] = __shfl_sync(0xffffffffu, att, h);
    float s = bias[lane];
    const float* xr = g_xh + (size_t)n * HC;
    #pragma unroll
    for (int h = 0; h < HH; h++) s = fmaf(atth[h], xr[h * CC + lane], s);
    out[n * CC + lane] = s;
}

// ---------------- K8: per-edge message scatter (octet layout, float4 reds) ----------------
// 8 threads per edge; thread q owns channels 4q..4q+3.
__global__ void k_edge3(float* __restrict__ out, int E) {
    int t = blockIdx.x * blockDim.x + threadIdx.x;
    int e = t >> 3;
    if (e >= E) return;
    int q = t & 7;
    int s = g_src[e], d = g_dst[e];

    float ex  = g_alpha[(size_t)e * HH + q];
    float den = g_denom[d * HH + q];
    float att = ex / den * (1.0f / HH);

    unsigned mask = __activemask();
    int obase = (threadIdx.x & 31) & ~7;   // octet base lane within warp

    float4 acc = make_float4(0.f, 0.f, 0.f, 0.f);
    const float4* xr = (const float4*)(g_xh + (size_t)s * HC) + q;
    #pragma unroll
    for (int h = 0; h < HH; h++) {
        float ath = __shfl_sync(mask, att, obase + h);
        float4 xv = xr[h * 8];             // xh[s, h, 4q..4q+3]
        acc.x = fmaf(ath, xv.x, acc.x);
        acc.y = fmaf(ath, xv.y, acc.y);
        acc.z = fmaf(ath, xv.z, acc.z);
        acc.w = fmaf(ath, xv.w, acc.w);
    }
    atomicAdd((float4*)(out + (size_t)d * CC + q * 4), acc);
}

// ---------------- launch ----------------
extern "C" void kernel_launch(void* const* d_in, const int* in_sizes, int n_in,
                              void* d_out, int out_size) {
    const float* x     = (const float*)d_in[0];
    const void*  ei    = d_in[1];
    const float* ea    = (const float*)d_in[2];
    const float* W     = (const float*)d_in[3];
    const float* We    = (const float*)d_in[4];
    const float* asrc  = (const float*)d_in[5];
    const float* adst  = (const float*)d_in[6];
    const float* aedge = (const float*)d_in[7];
    const float* bias  = (const float*)d_in[8];
    float* out = (float*)d_out;

    int fin = in_sizes[3] / HC;        // 128
    int N   = in_sizes[0] / fin;       // 50000
    int fe  = in_sizes[4] / HC;        // 16
    int E   = in_sizes[2] / fe;        // 800000
    if (N > MAXN) N = MAXN;
    if (E > MAXE) E = MAXE;

    k_detect<<<1, 256>>>((const unsigned int*)ei, 2 * E);
    k_convert<<<(E + 255) / 256, 256>>>(ei, E);
    k_M<<<1, 128>>>(We, aedge);
    k_init<<<(N * FE + 255) / 256, 256>>>(N);

    size_t smem = (size_t)(FIN * 128 + 16 * 128) * sizeof(float);  // 73728 B
    cudaFuncSetAttribute(k_gemm, cudaFuncAttributeMaxDynamicSharedMemorySize, (int)smem);
    dim3 ggrid((N + 127) / 128, 2);
    k_gemm<<<ggrid, 256, smem>>>(x, W, N);

    k_att_nodes<<<(N * HH + 255) / 256, 256>>>(asrc, adst, N);
    k_edge1<<<(E + 255) / 256, 256>>>(ea, E);
    k_node_out<<<(N * 32 + 255) / 256, 256>>>(bias, out, N);
    k_edge3<<<(E * 8 + 255) / 256, 256>>>(out, E);
}

// round 17
// speedup vs baseline: 1.1722x; 1.1722x over previous
#include <cuda_runtime.h>
#include <cuda_fp16.h>
#include <math.h>
#include <stdint.h>

// Problem constants (fixed by the reference)
#define HH   8      // heads
#define CC   32     // channels per head
#define HC   256    // H*C
#define FE   16     // edge feature dim
#define FIN  128    // input feature dim
#define NEG  0.2f

#define MAXN 50000
#define MAXE 800000

// ---------------- device scratch (no allocs allowed) ----------------
__device__ __align__(16) float  g_xh[(size_t)MAXN * HC];    // projected node features [N,H,C] fp32
__device__ __align__(16) __half g_xh16[(size_t)MAXN * HC];  // fp16 mirror for message gather
__device__ __align__(16) float g_asrc[MAXN * HH];
__device__ __align__(16) float g_adst[MAXN * HH];
__device__ __align__(16) float g_denom[MAXN * HH];
__device__ __align__(16) float g_loop[MAXN * FE];
__device__ float g_deg[MAXN];
__device__ __align__(16) float g_alpha[(size_t)MAXE * HH]; // per-edge exp(leaky(alpha))
__device__ int   g_src[MAXE];
__device__ int   g_dst[MAXE];
__device__ float g_M[FE * HH];                 // folded edge-attention matrix [F_e,H]
__device__ int   g_is64;

// ---------------- packed f32x2 helpers (sm_103a FFMA2) ----------------
__device__ __forceinline__ unsigned long long dup2(float a) {
    unsigned long long r;
    asm("mov.b64 %0, {%1, %1};" : "=l"(r) : "f"(a));
    return r;
}
__device__ __forceinline__ void ffma2(unsigned long long& d,
                                      unsigned long long a,
                                      unsigned long long b) {
    asm("fma.rn.f32x2 %0, %1, %2, %0;" : "+l"(d) : "l"(a), "l"(b));
}

// ---------------- K0: detect edge_index dtype (int64 vs int32) ----------------
__global__ void k_detect(const unsigned int* __restrict__ w, int nwords) {
    __shared__ unsigned int s[256];
    unsigned int acc = 0;
    for (int t = threadIdx.x; t < 1024; t += 256) {
        int idx = 2 * t + 1;
        if (idx < nwords) acc |= w[idx];
    }
    s[threadIdx.x] = acc;
    __syncthreads();
    for (int o = 128; o > 0; o >>= 1) {
        if (threadIdx.x < o) s[threadIdx.x] |= s[threadIdx.x + o];
        __syncthreads();
    }
    if (threadIdx.x == 0) g_is64 = (s[0] == 0u) ? 1 : 0;
}

// ---------------- K1: convert indices + init accumulators (fused) ----------------
__global__ void k_convert_init(const void* __restrict__ ei, int E, int N) {
    int i = blockIdx.x * blockDim.x + threadIdx.x;
    if (i < E) {
        int s, d;
        if (g_is64) {
            const long long* p = (const long long*)ei;
            s = (int)p[i];
            d = (int)p[(size_t)E + i];
        } else {
            const int* p = (const int*)ei;
            s = p[i];
            d = p[E + i];
        }
        g_src[i] = s;
        g_dst[i] = d;
    }
    if (i < N * FE) g_loop[i] = 0.0f;
    if (i < N * HH) g_denom[i] = 0.0f;
    if (i < N) g_deg[i] = 0.0f;
}

// ---------------- K2: folded edge-attn matrix M[f,h] ----------------
__global__ void k_M(const float* __restrict__ We, const float* __restrict__ ae) {
    int t = threadIdx.x;
    if (t >= FE * HH) return;
    int f = t / HH, h = t % HH;
    float s = 0.0f;
    #pragma unroll
    for (int c = 0; c < CC; c++)
        s = fmaf(We[(h * CC + c) * FE + f], ae[h * CC + c], s);
    g_M[f * HH + h] = s;
}

// ---------------- K4: GEMM xh = x @ W^T  via packed f32x2 ----------------
// Tile: 128 rows x 128 cols per CTA, 256 threads, 8 rows x 4 col-pairs per thread.
// 2 CTAs/SM (72KB smem each). Epilogue writes both fp32 and fp16 copies.
__global__ void __launch_bounds__(256, 2) k_gemm(const float* __restrict__ x,
                                                 const float* __restrict__ W,
                                                 int N) {
    extern __shared__ float sm[];
    float* ws = sm;                 // [128 k][128 c]  ws[k*128 + c]
    float* xs = sm + FIN * 128;     // [16 k][128 r]   xs[kk*128 + r]
    int tid = threadIdx.x;
    int tx  = tid & 15;             // col-pair group
    int ty  = tid >> 4;             // row group
    int rb  = blockIdx.x * 128;
    int cb  = blockIdx.y * 128;

    // load W tile: cols cb..cb+127, k = 0..127 (each thread: one col, half the k's)
    {
        int c  = tid & 127;
        int kh = (tid >> 7) * 64;
        const float* wp = W + (size_t)(cb + c) * FIN + kh;
        #pragma unroll
        for (int k4 = 0; k4 < 16; k4++) {
            float4 w = *(const float4*)(wp + k4 * 4);
            ws[(kh + k4 * 4 + 0) * 128 + c] = w.x;
            ws[(kh + k4 * 4 + 1) * 128 + c] = w.y;
            ws[(kh + k4 * 4 + 2) * 128 + c] = w.z;
            ws[(kh + k4 * 4 + 3) * 128 + c] = w.w;
        }
    }

    unsigned long long acc[8][4];
    #pragma unroll
    for (int i = 0; i < 8; i++)
        #pragma unroll
        for (int j = 0; j < 4; j++) acc[i][j] = 0ull;

    for (int kb = 0; kb < FIN / 16; kb++) {
        __syncthreads();   // also covers W visibility on first iteration
        {
            int r   = tid >> 1;
            int kq  = (tid & 1) * 8;
            int row = rb + r;
            if (row >= N) row = N - 1;          // clamp (stores are guarded)
            const float* xp = x + (size_t)row * FIN + kb * 16 + kq;
            float4 v0 = *(const float4*)(xp);
            float4 v1 = *(const float4*)(xp + 4);
            xs[(kq + 0) * 128 + r] = v0.x;
            xs[(kq + 1) * 128 + r] = v0.y;
            xs[(kq + 2) * 128 + r] = v0.z;
            xs[(kq + 3) * 128 + r] = v0.w;
            xs[(kq + 4) * 128 + r] = v1.x;
            xs[(kq + 5) * 128 + r] = v1.y;
            xs[(kq + 6) * 128 + r] = v1.z;
            xs[(kq + 7) * 128 + r] = v1.w;
        }
        __syncthreads();
        #pragma unroll
        for (int kk = 0; kk < 16; kk++) {
            unsigned long long x2[8], w2[4];
            #pragma unroll
            for (int i = 0; i < 8; i++)
                x2[i] = dup2(xs[kk * 128 + ty * 8 + i]);
            #pragma unroll
            for (int j = 0; j < 4; j++)
                w2[j] = *(const unsigned long long*)(ws + (kb * 16 + kk) * 128 + 2 * tx + 32 * j);
            #pragma unroll
            for (int i = 0; i < 8; i++)
                #pragma unroll
                for (int j = 0; j < 4; j++)
                    ffma2(acc[i][j], x2[i], w2[j]);
        }
    }

    #pragma unroll
    for (int i = 0; i < 8; i++) {
        int row = rb + ty * 8 + i;
        if (row < N) {
            #pragma unroll
            for (int j = 0; j < 4; j++) {
                float2 v = *(float2*)&acc[i][j];  // lo = col 2*tx, hi = col 2*tx+1
                size_t off = (size_t)row * HC + cb + 2 * tx + 32 * j;
                *(float2*)(g_xh + off) = v;
                *(__half2*)(g_xh16 + off) = __floats2half2_rn(v.x, v.y);
            }
        }
    }
}

// ---------------- K5: per-node a_src / a_dst ----------------
__global__ void k_att_nodes(const float* __restrict__ asrc_w,
                            const float* __restrict__ adst_w, int N) {
    int t = blockIdx.x * blockDim.x + threadIdx.x;
    if (t >= N * HH) return;
    int n = t >> 3, h = t & 7;
    const float4* row = (const float4*)(g_xh + (size_t)n * HC + h * CC);
    const float4* aw  = (const float4*)(asrc_w + h * CC);
    const float4* dw  = (const float4*)(adst_w + h * CC);
    float s = 0.0f, d = 0.0f;
    #pragma unroll
    for (int q = 0; q < CC / 4; q++) {
        float4 v = row[q];
        float4 a = __ldg(aw + q);
        float4 b = __ldg(dw + q);
        s = fmaf(v.x, a.x, s); s = fmaf(v.y, a.y, s);
        s = fmaf(v.z, a.z, s); s = fmaf(v.w, a.w, s);
        d = fmaf(v.x, b.x, d); d = fmaf(v.y, b.y, d);
        d = fmaf(v.z, b.z, d); d = fmaf(v.w, b.w, d);
    }
    g_asrc[t] = s;
    g_adst[t] = d;
}

// ---------------- K6: fused per-edge alpha->exp + denom + deg + loop_attr ----------------
// No softmax-max needed: |alpha| is small, exp(alpha)/sum(exp) == softmax exactly.
__global__ void k_edge1(const float* __restrict__ ea, int E) {
    __shared__ float Ms[FE * HH];
    if (threadIdx.x < FE * HH) Ms[threadIdx.x] = g_M[threadIdx.x];
    __syncthreads();
    int e = blockIdx.x * blockDim.x + threadIdx.x;
    if (e >= E) return;
    int s = g_src[e], d = g_dst[e];

    float4 av[4];
    const float4* p = (const float4*)(ea + (size_t)e * FE);
    #pragma unroll
    for (int q = 0; q < 4; q++) av[q] = p[q];
    float a[FE];
    *(float4*)(a + 0)  = av[0];
    *(float4*)(a + 4)  = av[1];
    *(float4*)(a + 8)  = av[2];
    *(float4*)(a + 12) = av[3];

    float4 s0 = *(const float4*)(g_asrc + s * HH);
    float4 s1 = *(const float4*)(g_asrc + s * HH + 4);
    float4 d0 = *(const float4*)(g_adst + d * HH);
    float4 d1 = *(const float4*)(g_adst + d * HH + 4);
    float sa[8] = {s0.x, s0.y, s0.z, s0.w, s1.x, s1.y, s1.z, s1.w};
    float da[8] = {d0.x, d0.y, d0.z, d0.w, d1.x, d1.y, d1.z, d1.w};

    float ex[8];
    #pragma unroll
    for (int h = 0; h < HH; h++) {
        float aeh = 0.0f;
        #pragma unroll
        for (int f = 0; f < FE; f++) aeh = fmaf(a[f], Ms[f * HH + h], aeh);
        float al = sa[h] + da[h] + aeh;
        al = (al >= 0.0f) ? al : NEG * al;
        ex[h] = __expf(al);
    }
    float4 e0 = make_float4(ex[0], ex[1], ex[2], ex[3]);
    float4 e1 = make_float4(ex[4], ex[5], ex[6], ex[7]);
    *(float4*)(g_alpha + (size_t)e * HH)     = e0;
    *(float4*)(g_alpha + (size_t)e * HH + 4) = e1;

    atomicAdd((float4*)(g_denom + d * HH),     e0);
    atomicAdd((float4*)(g_denom + d * HH + 4), e1);
    #pragma unroll
    for (int q = 0; q < 4; q++)
        atomicAdd((float4*)(g_loop + d * FE + q * 4), av[q]);
    atomicAdd(&g_deg[d], 1.0f);
}

// ---------------- K7: per-node self-loop + finalize denom + output init ----------------
// One warp per node. Lane = output channel. Lanes 0..7 also handle heads.
__global__ void k_node_out(const float* __restrict__ bias, float* __restrict__ out, int N) {
    int lane = threadIdx.x & 31;
    int n = (blockIdx.x * blockDim.x + threadIdx.x) >> 5;
    if (n >= N) return;
    float att = 0.0f;
    float invdeg = 1.0f / fmaxf(g_deg[n], 1.0f);
    if (lane < HH) {
        int h = lane;
        float aeh = 0.0f;
        #pragma unroll
        for (int f = 0; f < FE; f++)
            aeh = fmaf(g_loop[n * FE + f] * invdeg, g_M[f * HH + h], aeh);
        float al = g_asrc[n * HH + h] + g_adst[n * HH + h] + aeh;
        al = (al >= 0.0f) ? al : NEG * al;
        float ex  = __expf(al);
        float den = g_denom[n * HH + h] + ex;
        g_denom[n * HH + h] = den;        // finalize denom for K8
        att = ex / den * (1.0f / HH);
    }
    float atth[HH];
    #pragma unroll
    for (int h = 0; h < HH; h++) atth[h] = __shfl_sync(0xffffffffu, att, h);
    float s = bias[lane];
    const float* xr = g_xh + (size_t)n * HC;
    #pragma unroll
    for (int h = 0; h < HH; h++) s = fmaf(atth[h], xr[h * CC + lane], s);
    out[n * CC + lane] = s;
}

// ---------------- K8: per-edge message scatter (octet layout, fp16 gather) ----------------
// 8 threads per edge; thread q owns channels 4q..4q+3. xh gathered as fp16 -> half traffic.
__global__ void k_edge3(float* __restrict__ out, int E) {
    int t = blockIdx.x * blockDim.x + threadIdx.x;
    int e = t >> 3;
    if (e >= E) return;
    int q = t & 7;
    int s = g_src[e], d = g_dst[e];

    float ex  = g_alpha[(size_t)e * HH + q];
    float den = g_denom[d * HH + q];
    float att = ex / den * (1.0f / HH);

    unsigned mask = __activemask();
    int obase = (threadIdx.x & 31) & ~7;   // octet base lane within warp

    float4 acc = make_float4(0.f, 0.f, 0.f, 0.f);
    const uint2* xr = (const uint2*)(g_xh16 + (size_t)s * HC + 4 * q);  // 8B: 4 halves
    #pragma unroll
    for (int h = 0; h < HH; h++) {
        float ath = __shfl_sync(mask, att, obase + h);
        uint2 v = xr[h * 8];               // xh16[s, h, 4q..4q+3] (h*32 halves = h*8 uint2)
        float2 f01 = __half22float2(*(const __half2*)&v.x);
        float2 f23 = __half22float2(*(const __half2*)&v.y);
        acc.x = fmaf(ath, f01.x, acc.x);
        acc.y = fmaf(ath, f01.y, acc.y);
        acc.z = fmaf(ath, f23.x, acc.z);
        acc.w = fmaf(ath, f23.y, acc.w);
    }
    atomicAdd((float4*)(out + (size_t)d * CC + q * 4), acc);
}

// ---------------- launch ----------------
extern "C" void kernel_launch(void* const* d_in, const int* in_sizes, int n_in,
                              void* d_out, int out_size) {
    const float* x     = (const float*)d_in[0];
    const void*  ei    = d_in[1];
    const float* ea    = (const float*)d_in[2];
    const float* W     = (const float*)d_in[3];
    const float* We    = (const float*)d_in[4];
    const float* asrc  = (const float*)d_in[5];
    const float* adst  = (const float*)d_in[6];
    const float* aedge = (const float*)d_in[7];
    const float* bias  = (const float*)d_in[8];
    float* out = (float*)d_out;

    int fin = in_sizes[3] / HC;        // 128
    int N   = in_sizes[0] / fin;       // 50000
    int fe  = in_sizes[4] / HC;        // 16
    int E   = in_sizes[2] / fe;        // 800000
    if (N > MAXN) N = MAXN;
    if (E > MAXE) E = MAXE;

    k_detect<<<1, 256>>>((const unsigned int*)ei, 2 * E);
    int ci = (E > N * FE) ? E : N * FE;
    k_convert_init<<<(ci + 255) / 256, 256>>>(ei, E, N);
    k_M<<<1, 128>>>(We, aedge);

    size_t smem = (size_t)(FIN * 128 + 16 * 128) * sizeof(float);  // 73728 B
    cudaFuncSetAttribute(k_gemm, cudaFuncAttributeMaxDynamicSharedMemorySize, (int)smem);
    dim3 ggrid((N + 127) / 128, 2);
    k_gemm<<<ggrid, 256, smem>>>(x, W, N);

    k_att_nodes<<<(N * HH + 255) / 256, 256>>>(asrc, adst, N);
    k_edge1<<<(E + 255) / 256, 256>>>(ea, E);
    k_node_out<<<(N * 32 + 255) / 256, 256>>>(bias, out, N);
    k_edge3<<<(E * 8 + 255) / 256, 256>>>(out, E);
}